// round 15
// baseline (speedup 1.0000x reference)
// R15 = R14 resubmission. R14 bench died with the recurring broker/container
// infra error ("GB300 container failed twice", no harness output) — same
// signature as R1/R5/R10, each of which passed on unchanged resubmission.
// Kernel identical to R14: R11 structure + pre-split bf16 weights (L1-resident,
// no W smem fill) + 256-thread 128x128 GEMM blocks (g1 y 4->2, g2 2->1).
#include <cuda_runtime.h>
#include <cuda_bf16.h>
#include <math.h>
#include <stdlib.h>

#define NN 100000
#define EE 3200000
#define GG 128
#define CC 128
#define LL 4
#define SCAN_B 98

// ---------------- eager module loading policy (see R7) ----------------
namespace {
struct EnvSetter {
    EnvSetter() { setenv("CUDA_MODULE_LOADING", "EAGER", 1); }
};
EnvSetter g_env_setter;
}  // namespace

// ---------------- scratch ----------------
__device__ float d_bufP[NN * CC];
__device__ float d_bufQ[NN * CC];
__device__ float d_bufR[NN * CC];
__device__ float d_g [GG * CC];
__device__ int   d_deg[NN];
__device__ int   d_rowptr[NN + 1];
__device__ int   d_cursor[NN];
__device__ int   d_bsum[SCAN_B];
__device__ int   d_col[EE];
// pre-split weights: [l][n][kp] packed bf16x2 {W[2kp][n], W[2kp+1][n]}
__device__ unsigned d_W1h[LL * 256 * 64], d_W1l[LL * 256 * 64];
__device__ unsigned d_W2h[LL * 128 * 128], d_W2l[LL * 128 * 128];

__device__ __forceinline__ float* bufById(int id) {
    return id == 0 ? d_bufP : (id == 1 ? d_bufQ : d_bufR);
}

// ---------------- bf16 split + mma helpers ----------------
__device__ __forceinline__ void split2(float x0, float x1,
                                       unsigned& hi, unsigned& lo) {
    __nv_bfloat16 h0 = __float2bfloat16(x0);
    __nv_bfloat16 h1 = __float2bfloat16(x1);
    float r0 = x0 - __bfloat162float(h0);
    float r1 = x1 - __bfloat162float(h1);
    __nv_bfloat162 hp; hp.x = h0; hp.y = h1;
    __nv_bfloat162 lp; lp.x = __float2bfloat16(r0); lp.y = __float2bfloat16(r1);
    hi = *reinterpret_cast<unsigned*>(&hp);
    lo = *reinterpret_cast<unsigned*>(&lp);
}

__device__ __forceinline__ void mma_bf16(float* c, const unsigned* a,
                                         unsigned b0, unsigned b1) {
    asm volatile(
        "mma.sync.aligned.m16n8k16.row.col.f32.bf16.bf16.f32 "
        "{%0,%1,%2,%3}, {%4,%5,%6,%7}, {%8,%9}, {%0,%1,%2,%3};"
        : "+f"(c[0]), "+f"(c[1]), "+f"(c[2]), "+f"(c[3])
        : "r"(a[0]), "r"(a[1]), "r"(a[2]), "r"(a[3]), "r"(b0), "r"(b1));
}

#define RSW 9   // A-tile row stride in words (8 k-pairs + pad)

// ---------------- utility ----------------
__global__ void zero_deg_kernel() {
    int i = blockIdx.x * blockDim.x + threadIdx.x;
    if (i < NN) d_deg[i] = 0;
}
__global__ void zero_g_kernel() {
    int i = blockIdx.x * blockDim.x + threadIdx.x;
    if (i < GG * CC) d_g[i] = 0.f;
}

// ---------------- weight pre-split ----------------
__global__ void wsplit1_kernel(const float* __restrict__ W1) {
    int idx = blockIdx.x * blockDim.x + threadIdx.x;
    if (idx >= LL * 256 * 64) return;
    int l = idx / (256 * 64);
    int rem = idx - l * 256 * 64;
    int n = rem >> 6, kp = rem & 63;
    const float* base = W1 + l * 128 * 256;
    unsigned hi, lo;
    split2(base[(2 * kp) * 256 + n], base[(2 * kp + 1) * 256 + n], hi, lo);
    d_W1h[idx] = hi; d_W1l[idx] = lo;
}
__global__ void wsplit2_kernel(const float* __restrict__ W2) {
    int idx = blockIdx.x * blockDim.x + threadIdx.x;
    if (idx >= LL * 128 * 128) return;
    int l = idx / (128 * 128);
    int rem = idx - l * 128 * 128;
    int n = rem >> 7, kp = rem & 127;
    const float* base = W2 + l * 256 * 128;
    unsigned hi, lo;
    split2(base[(2 * kp) * 128 + n], base[(2 * kp + 1) * 128 + n], hi, lo);
    d_W2h[idx] = hi; d_W2l[idx] = lo;
}

// ---------------- node transform ----------------
__global__ void node_transform_kernel(const float* __restrict__ x,
                                      const float* __restrict__ ntW,
                                      const float* __restrict__ ntb) {
    int idx = blockIdx.x * blockDim.x + threadIdx.x;
    if (idx >= NN * CC) return;
    int i = idx >> 7;
    int c = idx & (CC - 1);
    float x0 = x[2 * i], x1 = x[2 * i + 1];
    d_bufP[idx] = x0 * ntW[c] + x1 * ntW[CC + c] + ntb[c];
}

// ---------------- CSR build ----------------
__global__ void degree_kernel(const int* __restrict__ dst) {
    int e = blockIdx.x * blockDim.x + threadIdx.x;
    if (e < EE) atomicAdd(&d_deg[dst[e]], 1);
}

__global__ void scan1_kernel() {
    __shared__ int sh[1024];
    int t = threadIdx.x;
    int i = blockIdx.x * 1024 + t;
    sh[t] = (i < NN) ? d_deg[i] : 0;
    __syncthreads();
    for (int off = 512; off > 0; off >>= 1) {
        if (t < off) sh[t] += sh[t + off];
        __syncthreads();
    }
    if (t == 0) d_bsum[blockIdx.x] = sh[0];
}
__global__ void scan2_kernel() {
    __shared__ int sh[128];
    int t = threadIdx.x;
    int v = (t < SCAN_B) ? d_bsum[t] : 0;
    sh[t] = v;
    __syncthreads();
    for (int off = 1; off < 128; off <<= 1) {
        int x = (t >= off) ? sh[t - off] : 0;
        __syncthreads();
        sh[t] += x;
        __syncthreads();
    }
    if (t < SCAN_B) d_bsum[t] = sh[t] - v;
    if (t == 127) d_rowptr[NN] = sh[127];
}
__global__ void scan3_kernel() {
    __shared__ int sh[1024];
    int t = threadIdx.x;
    int i = blockIdx.x * 1024 + t;
    int v = (i < NN) ? d_deg[i] : 0;
    sh[t] = v;
    __syncthreads();
    for (int off = 1; off < 1024; off <<= 1) {
        int x = (t >= off) ? sh[t - off] : 0;
        __syncthreads();
        sh[t] += x;
        __syncthreads();
    }
    if (i < NN) {
        int ex = sh[t] - v + d_bsum[blockIdx.x];
        d_rowptr[i] = ex;
        d_cursor[i] = ex;
    }
}

__global__ void fill_kernel(const int* __restrict__ src, const int* __restrict__ dst) {
    int e = blockIdx.x * blockDim.x + threadIdx.x;
    if (e >= EE) return;
    int d = dst[e];
    int p = atomicAdd(&d_cursor[d], 1);
    d_col[p] = src[e];
}

// ---------------- aggregation (R11 form) ----------------
__global__ void aggregate_kernel(int inSel, int outSel) {
    int gwarp = (blockIdx.x * blockDim.x + threadIdx.x) >> 5;
    int lane = threadIdx.x & 31;
    if (gwarp >= NN) return;
    const float4* __restrict__ h4 = (const float4*)bufById(inSel);
    float4* __restrict__ o4 = (float4*)bufById(outSel);
    float4 acc = __ldg(&h4[gwarp * 32 + lane]);
    int beg = __ldg(&d_rowptr[gwarp]);
    int end = __ldg(&d_rowptr[gwarp + 1]);
    int e = beg;
    for (; e + 8 <= end; e += 8) {
        int s[8];
#pragma unroll
        for (int j = 0; j < 8; j++) s[j] = __ldg(&d_col[e + j]);
#pragma unroll
        for (int j = 0; j < 8; j++) {
            float4 v = __ldg(&h4[s[j] * 32 + lane]);
            acc.x += v.x; acc.y += v.y; acc.z += v.z; acc.w += v.w;
        }
    }
    for (; e < end; e++) {
        int s0 = __ldg(&d_col[e]);
        float4 v = __ldg(&h4[s0 * 32 + lane]);
        acc.x += v.x; acc.y += v.y; acc.z += v.z; acc.w += v.w;
    }
    o4[gwarp * 32 + lane] = acc;
}

// ---- shared A-tile fill: 128 rows x 16 k (one k-tile) of fp32 -> split bf16 --
__device__ __forceinline__ void fillA(unsigned* AhS, unsigned* AlS,
                                      const float* A, int rowBase, int k0,
                                      int tid) {
    int row = tid >> 1, kh = tid & 1;      // 2 threads/row, 8 floats each
    float4 v0, v1;
    if (rowBase + row < NN) {
        const float4* src = (const float4*)&A[(rowBase + row) * 128 + k0 + kh * 8];
        v0 = __ldg(src); v1 = __ldg(src + 1);
    } else {
        v0 = make_float4(0.f, 0.f, 0.f, 0.f);
        v1 = v0;
    }
    unsigned hi, lo;
    int base = row * RSW + kh * 4;
    split2(v0.x, v0.y, hi, lo); AhS[base + 0] = hi; AlS[base + 0] = lo;
    split2(v0.z, v0.w, hi, lo); AhS[base + 1] = hi; AlS[base + 1] = lo;
    split2(v1.x, v1.y, hi, lo); AhS[base + 2] = hi; AlS[base + 2] = lo;
    split2(v1.z, v1.w, hi, lo); AhS[base + 3] = hi; AlS[base + 3] = lo;
}

// =============== GEMM1: relu(BN(z0 @ W1 + b1)), 256 thr, 128x128 =============
// grid (782, 2): y = column half -> out buf oSelLo / oSelHi. W frags from
// pre-split globals (L1-resident).
__global__ void __launch_bounds__(256)
gemm1_kernel(int aSel, int l, const float* __restrict__ bias,
             const float* __restrict__ gma, const float* __restrict__ bta,
             int oSelLo, int oSelHi) {
    __shared__ unsigned AhS[128 * RSW], AlS[128 * RSW];
    const float* A = bufById(aSel);
    const unsigned* __restrict__ Wh = d_W1h + l * 16384;
    const unsigned* __restrict__ Wl = d_W1l + l * 16384;
    const int tid = threadIdx.x;
    const int lane = tid & 31, warp = tid >> 5;
    const int mi = warp & 3, ni = warp >> 2;     // 4 m-warps x 2 n-warps
    const int rowBase = blockIdx.x * 128;
    const int colBase = blockIdx.y * 128;
    const int g = lane >> 2, tg = lane & 3;

    float acc[2][8][4];
#pragma unroll
    for (int m = 0; m < 2; m++)
#pragma unroll
        for (int nf = 0; nf < 8; nf++)
#pragma unroll
            for (int q = 0; q < 4; q++) acc[m][nf][q] = 0.f;

#pragma unroll 1
    for (int t = 0; t < 8; t++) {
        __syncthreads();
        fillA(AhS, AlS, A, rowBase, t * 16, tid);
        __syncthreads();

        unsigned ah[2][4], al[2][4];
#pragma unroll
        for (int mf = 0; mf < 2; mf++) {
            int rb = mi * 32 + mf * 16;
            int w0 = (rb + g) * RSW, w1 = (rb + g + 8) * RSW;
            ah[mf][0] = AhS[w0 + tg];     ah[mf][1] = AhS[w1 + tg];
            ah[mf][2] = AhS[w0 + 4 + tg]; ah[mf][3] = AhS[w1 + 4 + tg];
            al[mf][0] = AlS[w0 + tg];     al[mf][1] = AlS[w1 + tg];
            al[mf][2] = AlS[w0 + 4 + tg]; al[mf][3] = AlS[w1 + 4 + tg];
        }
        int kb = t * 8;
#pragma unroll
        for (int nf = 0; nf < 8; nf++) {
            int col_g = colBase + ni * 64 + nf * 8 + g;
            unsigned bh0 = __ldg(&Wh[col_g * 64 + kb + tg]);
            unsigned bh1 = __ldg(&Wh[col_g * 64 + kb + 4 + tg]);
            unsigned bl0 = __ldg(&Wl[col_g * 64 + kb + tg]);
            unsigned bl1 = __ldg(&Wl[col_g * 64 + kb + 4 + tg]);
#pragma unroll
            for (int mf = 0; mf < 2; mf++) {
                mma_bf16(acc[mf][nf], ah[mf], bh0, bh1);
                mma_bf16(acc[mf][nf], ah[mf], bl0, bl1);
                mma_bf16(acc[mf][nf], al[mf], bh0, bh1);
            }
        }
    }

    float* Co = bufById(blockIdx.y == 0 ? oSelLo : oSelHi);
#pragma unroll
    for (int nf = 0; nf < 8; nf++) {
        int colL = ni * 64 + nf * 8 + tg * 2;
        int colG = colBase + colL;
        float b0 = bias[colG], b1 = bias[colG + 1];
        float g0 = gma[colG],  g1 = gma[colG + 1];
        float e0 = bta[colG],  e1 = bta[colG + 1];
#pragma unroll
        for (int mf = 0; mf < 2; mf++) {
            int r0 = rowBase + mi * 32 + mf * 16 + g;
            if (r0 < NN) {
                float2 v;
                v.x = fmaxf((acc[mf][nf][0] + b0) * g0 + e0, 0.f);
                v.y = fmaxf((acc[mf][nf][1] + b1) * g1 + e1, 0.f);
                *(float2*)&Co[r0 * 128 + colL] = v;
            }
            int r1 = r0 + 8;
            if (r1 < NN) {
                float2 v;
                v.x = fmaxf((acc[mf][nf][2] + b0) * g0 + e0, 0.f);
                v.y = fmaxf((acc[mf][nf][3] + b1) * g1 + e1, 0.f);
                *(float2*)&Co[r1 * 128 + colL] = v;
            }
        }
    }
}

// =============== GEMM2: relu(hidden @ W2 + b2), 256 thr, 128x128 ==============
// grid (782, 1): full 128 output cols; A = lo half (aSelLo) then hi (aSelHi).
__global__ void __launch_bounds__(256)
gemm2_kernel(int aSelLo, int aSelHi, int l, const float* __restrict__ bias,
             int oSel) {
    __shared__ unsigned AhS[128 * RSW], AlS[128 * RSW];
    const unsigned* __restrict__ Wh = d_W2h + l * 16384;
    const unsigned* __restrict__ Wl = d_W2l + l * 16384;
    float* Co = bufById(oSel);
    const int tid = threadIdx.x;
    const int lane = tid & 31, warp = tid >> 5;
    const int mi = warp & 3, ni = warp >> 2;
    const int rowBase = blockIdx.x * 128;
    const int g = lane >> 2, tg = lane & 3;

    float acc[2][8][4];
#pragma unroll
    for (int m = 0; m < 2; m++)
#pragma unroll
        for (int nf = 0; nf < 8; nf++)
#pragma unroll
            for (int q = 0; q < 4; q++) acc[m][nf][q] = 0.f;

#pragma unroll 1
    for (int t = 0; t < 16; t++) {
        const float* A = bufById(t < 8 ? aSelLo : aSelHi);
        __syncthreads();
        fillA(AhS, AlS, A, rowBase, (t & 7) * 16, tid);
        __syncthreads();

        unsigned ah[2][4], al[2][4];
#pragma unroll
        for (int mf = 0; mf < 2; mf++) {
            int rb = mi * 32 + mf * 16;
            int w0 = (rb + g) * RSW, w1 = (rb + g + 8) * RSW;
            ah[mf][0] = AhS[w0 + tg];     ah[mf][1] = AhS[w1 + tg];
            ah[mf][2] = AhS[w0 + 4 + tg]; ah[mf][3] = AhS[w1 + 4 + tg];
            al[mf][0] = AlS[w0 + tg];     al[mf][1] = AlS[w1 + tg];
            al[mf][2] = AlS[w0 + 4 + tg]; al[mf][3] = AlS[w1 + 4 + tg];
        }
        int kb = t * 8;   // kp index within K=256 (0..127)
#pragma unroll
        for (int nf = 0; nf < 8; nf++) {
            int col_g = ni * 64 + nf * 8 + g;
            unsigned bh0 = __ldg(&Wh[col_g * 128 + kb + tg]);
            unsigned bh1 = __ldg(&Wh[col_g * 128 + kb + 4 + tg]);
            unsigned bl0 = __ldg(&Wl[col_g * 128 + kb + tg]);
            unsigned bl1 = __ldg(&Wl[col_g * 128 + kb + 4 + tg]);
#pragma unroll
            for (int mf = 0; mf < 2; mf++) {
                mma_bf16(acc[mf][nf], ah[mf], bh0, bh1);
                mma_bf16(acc[mf][nf], ah[mf], bl0, bl1);
                mma_bf16(acc[mf][nf], al[mf], bh0, bh1);
            }
        }
    }

#pragma unroll
    for (int nf = 0; nf < 8; nf++) {
        int col = ni * 64 + nf * 8 + tg * 2;
        float b0 = bias[col], b1 = bias[col + 1];
#pragma unroll
        for (int mf = 0; mf < 2; mf++) {
            int r0 = rowBase + mi * 32 + mf * 16 + g;
            if (r0 < NN) {
                float2 v;
                v.x = fmaxf(acc[mf][nf][0] + b0, 0.f);
                v.y = fmaxf(acc[mf][nf][1] + b1, 0.f);
                *(float2*)&Co[r0 * 128 + col] = v;
            }
            int r1 = r0 + 8;
            if (r1 < NN) {
                float2 v;
                v.x = fmaxf(acc[mf][nf][2] + b0, 0.f);
                v.y = fmaxf(acc[mf][nf][3] + b1, 0.f);
                *(float2*)&Co[r1 * 128 + col] = v;
            }
        }
    }
}

// ---------------- pooling (reads P) ----------------
__global__ void pool_kernel(const int* __restrict__ batch0) {
    int c = threadIdx.x;
    int start = blockIdx.x * 128;
    if (start >= NN) return;
    int end = start + 128; if (end > NN) end = NN;
    int cur = __ldg(&batch0[start]);
    float acc = 0.f;
    for (int i = start; i < end; i++) {
        int b = __ldg(&batch0[i]);
        float v = d_bufP[i * CC + c];
        if (b != cur) {
            atomicAdd(&d_g[cur * CC + c], acc);
            acc = 0.f;
            cur = b;
        }
        acc += v;
    }
    atomicAdd(&d_g[cur * CC + c], acc);
}

// ---------------- MLP head + log_softmax ----------------
__global__ void mlp_kernel(const float* __restrict__ pW1, const float* __restrict__ pb1,
                           const float* __restrict__ pW2, const float* __restrict__ pb2,
                           float* __restrict__ out) {
    __shared__ float sg[128];
    __shared__ float r0s[64], r1s[64];
    int gi = blockIdx.x, t = threadIdx.x;
    sg[t]      = d_g[gi * CC + t];
    sg[t + 64] = d_g[gi * CC + t + 64];
    __syncthreads();
    float acc = pb1[t];
#pragma unroll 8
    for (int k = 0; k < 128; k++) acc += sg[k] * pW1[k * 64 + t];
    float q = acc > 0.f ? acc : (expf(acc) - 1.f);
    r0s[t] = q * pW2[t * 2 + 0];
    r1s[t] = q * pW2[t * 2 + 1];
    __syncthreads();
    for (int off = 32; off > 0; off >>= 1) {
        if (t < off) { r0s[t] += r0s[t + off]; r1s[t] += r1s[t + off]; }
        __syncthreads();
    }
    if (t == 0) {
        float y0 = r0s[0] + pb2[0];
        float y1 = r1s[0] + pb2[1];
        float m = fmaxf(y0, y1);
        float lse = m + logf(expf(y0 - m) + expf(y1 - m));
        out[gi * 2 + 0] = y0 - lse;
        out[gi * 2 + 1] = y1 - lse;
    }
}

// ---------------- launch ----------------
extern "C" void kernel_launch(void* const* d_in, const int* in_sizes, int n_in,
                              void* d_out, int out_size) {
    const float* x    = (const float*)d_in[0];
    const int*   ei   = (const int*)  d_in[1];
    const int*   bat  = (const int*)  d_in[2];
    const float* ntW  = (const float*)d_in[3];
    const float* ntb  = (const float*)d_in[4];
    const float* W1   = (const float*)d_in[5];
    const float* b1   = (const float*)d_in[6];
    const float* g1   = (const float*)d_in[7];
    const float* be1  = (const float*)d_in[8];
    const float* W2   = (const float*)d_in[9];
    const float* b2   = (const float*)d_in[10];
    const float* pW1  = (const float*)d_in[11];
    const float* pb1  = (const float*)d_in[12];
    const float* pW2  = (const float*)d_in[13];
    const float* pb2  = (const float*)d_in[14];
    float* out = (float*)d_out;

    const int* src = ei;
    const int* dst = ei + EE;

    zero_deg_kernel<<<(NN + 255) / 256, 256>>>();
    node_transform_kernel<<<(NN * CC + 255) / 256, 256>>>(x, ntW, ntb);  // -> P
    wsplit1_kernel<<<(LL * 256 * 64 + 255) / 256, 256>>>(W1);
    wsplit2_kernel<<<(LL * 128 * 128 + 255) / 256, 256>>>(W2);
    degree_kernel<<<(EE + 255) / 256, 256>>>(dst);
    scan1_kernel<<<SCAN_B, 1024>>>();
    scan2_kernel<<<1, 128>>>();
    scan3_kernel<<<SCAN_B, 1024>>>();
    fill_kernel<<<(EE + 255) / 256, 256>>>(src, dst);

    dim3 grid1((NN + 127) / 128, 2);
    dim3 grid2((NN + 127) / 128, 1);
    // Rotation (R11): even layer: h=P -> agg Q -> hidden (P,R) -> h=Q
    //                 odd  layer: h=Q -> agg P -> hidden (Q,R) -> h=P
    for (int l = 0; l < LL; l++) {
        int hin  = (l & 1) ? 1 : 0;
        int zbuf = (l & 1) ? 0 : 1;
        aggregate_kernel<<<(NN + 7) / 8, 256>>>(hin, zbuf);
        gemm1_kernel<<<grid1, 256>>>(zbuf, l, b1 + l * 2 * CC, g1 + l * 2 * CC,
                                     be1 + l * 2 * CC, hin, 2);
        gemm2_kernel<<<grid2, 256>>>(hin, 2, l, b2 + l * CC, zbuf);
    }
    // Final h in P after layer 3.

    zero_g_kernel<<<(GG * CC + 255) / 256, 256>>>();
    pool_kernel<<<(NN + 127) / 128, 128>>>(bat);
    mlp_kernel<<<GG, 64>>>(pW1, pb1, pW2, pb2, out);
}

// round 16
// speedup vs baseline: 1.2850x; 1.2850x over previous
// R16: revert R15/R14 W-from-global regression (L1 latency in mma chain).
// Exact R11 structure + double-buffered smem tiles in both GEMMs: tile t+1's
// global loads issue into registers during tile t's mma, one sync per tile.
#include <cuda_runtime.h>
#include <cuda_bf16.h>
#include <math.h>
#include <stdlib.h>

#define NN 100000
#define EE 3200000
#define GG 128
#define CC 128
#define LL 4
#define SCAN_B 98

// ---------------- eager module loading policy (see R7) ----------------
namespace {
struct EnvSetter {
    EnvSetter() { setenv("CUDA_MODULE_LOADING", "EAGER", 1); }
};
EnvSetter g_env_setter;
}  // namespace

// ---------------- scratch ----------------
__device__ float d_bufP[NN * CC];
__device__ float d_bufQ[NN * CC];
__device__ float d_bufR[NN * CC];
__device__ float d_g [GG * CC];
__device__ int   d_deg[NN];
__device__ int   d_rowptr[NN + 1];
__device__ int   d_cursor[NN];
__device__ int   d_bsum[SCAN_B];
__device__ int   d_col[EE];

__device__ __forceinline__ float* bufById(int id) {
    return id == 0 ? d_bufP : (id == 1 ? d_bufQ : d_bufR);
}

// ---------------- bf16 split + mma helpers ----------------
__device__ __forceinline__ void split2(float x0, float x1,
                                       unsigned& hi, unsigned& lo) {
    __nv_bfloat16 h0 = __float2bfloat16(x0);
    __nv_bfloat16 h1 = __float2bfloat16(x1);
    float r0 = x0 - __bfloat162float(h0);
    float r1 = x1 - __bfloat162float(h1);
    __nv_bfloat162 hp; hp.x = h0; hp.y = h1;
    __nv_bfloat162 lp; lp.x = __float2bfloat16(r0); lp.y = __float2bfloat16(r1);
    hi = *reinterpret_cast<unsigned*>(&hp);
    lo = *reinterpret_cast<unsigned*>(&lp);
}

__device__ __forceinline__ void mma_bf16(float* c, const unsigned* a,
                                         unsigned b0, unsigned b1) {
    asm volatile(
        "mma.sync.aligned.m16n8k16.row.col.f32.bf16.bf16.f32 "
        "{%0,%1,%2,%3}, {%4,%5,%6,%7}, {%8,%9}, {%0,%1,%2,%3};"
        : "+f"(c[0]), "+f"(c[1]), "+f"(c[2]), "+f"(c[3])
        : "r"(a[0]), "r"(a[1]), "r"(a[2]), "r"(a[3]), "r"(b0), "r"(b1));
}

#define RSW 9   // smem row stride in 32-bit words (conflict-free frags)

// ---------------- utility ----------------
__global__ void zero_deg_kernel() {
    int i = blockIdx.x * blockDim.x + threadIdx.x;
    if (i < NN) d_deg[i] = 0;
}
__global__ void zero_g_kernel() {
    int i = blockIdx.x * blockDim.x + threadIdx.x;
    if (i < GG * CC) d_g[i] = 0.f;
}

// ---------------- node transform ----------------
__global__ void node_transform_kernel(const float* __restrict__ x,
                                      const float* __restrict__ ntW,
                                      const float* __restrict__ ntb) {
    int idx = blockIdx.x * blockDim.x + threadIdx.x;
    if (idx >= NN * CC) return;
    int i = idx >> 7;
    int c = idx & (CC - 1);
    float x0 = x[2 * i], x1 = x[2 * i + 1];
    d_bufP[idx] = x0 * ntW[c] + x1 * ntW[CC + c] + ntb[c];
}

// ---------------- CSR build ----------------
__global__ void degree_kernel(const int* __restrict__ dst) {
    int e = blockIdx.x * blockDim.x + threadIdx.x;
    if (e < EE) atomicAdd(&d_deg[dst[e]], 1);
}

__global__ void scan1_kernel() {
    __shared__ int sh[1024];
    int t = threadIdx.x;
    int i = blockIdx.x * 1024 + t;
    sh[t] = (i < NN) ? d_deg[i] : 0;
    __syncthreads();
    for (int off = 512; off > 0; off >>= 1) {
        if (t < off) sh[t] += sh[t + off];
        __syncthreads();
    }
    if (t == 0) d_bsum[blockIdx.x] = sh[0];
}
__global__ void scan2_kernel() {
    __shared__ int sh[128];
    int t = threadIdx.x;
    int v = (t < SCAN_B) ? d_bsum[t] : 0;
    sh[t] = v;
    __syncthreads();
    for (int off = 1; off < 128; off <<= 1) {
        int x = (t >= off) ? sh[t - off] : 0;
        __syncthreads();
        sh[t] += x;
        __syncthreads();
    }
    if (t < SCAN_B) d_bsum[t] = sh[t] - v;
    if (t == 127) d_rowptr[NN] = sh[127];
}
__global__ void scan3_kernel() {
    __shared__ int sh[1024];
    int t = threadIdx.x;
    int i = blockIdx.x * 1024 + t;
    int v = (i < NN) ? d_deg[i] : 0;
    sh[t] = v;
    __syncthreads();
    for (int off = 1; off < 1024; off <<= 1) {
        int x = (t >= off) ? sh[t - off] : 0;
        __syncthreads();
        sh[t] += x;
        __syncthreads();
    }
    if (i < NN) {
        int ex = sh[t] - v + d_bsum[blockIdx.x];
        d_rowptr[i] = ex;
        d_cursor[i] = ex;
    }
}

__global__ void fill_kernel(const int* __restrict__ src, const int* __restrict__ dst) {
    int e = blockIdx.x * blockDim.x + threadIdx.x;
    if (e >= EE) return;
    int d = dst[e];
    int p = atomicAdd(&d_cursor[d], 1);
    d_col[p] = src[e];
}

// ---------------- aggregation (R11 form) ----------------
__global__ void aggregate_kernel(int inSel, int outSel) {
    int gwarp = (blockIdx.x * blockDim.x + threadIdx.x) >> 5;
    int lane = threadIdx.x & 31;
    if (gwarp >= NN) return;
    const float4* __restrict__ h4 = (const float4*)bufById(inSel);
    float4* __restrict__ o4 = (float4*)bufById(outSel);
    float4 acc = __ldg(&h4[gwarp * 32 + lane]);
    int beg = __ldg(&d_rowptr[gwarp]);
    int end = __ldg(&d_rowptr[gwarp + 1]);
    int e = beg;
    for (; e + 8 <= end; e += 8) {
        int s[8];
#pragma unroll
        for (int j = 0; j < 8; j++) s[j] = __ldg(&d_col[e + j]);
#pragma unroll
        for (int j = 0; j < 8; j++) {
            float4 v = __ldg(&h4[s[j] * 32 + lane]);
            acc.x += v.x; acc.y += v.y; acc.z += v.z; acc.w += v.w;
        }
    }
    for (; e < end; e++) {
        int s0 = __ldg(&d_col[e]);
        float4 v = __ldg(&h4[s0 * 32 + lane]);
        acc.x += v.x; acc.y += v.y; acc.z += v.z; acc.w += v.w;
    }
    o4[gwarp * 32 + lane] = acc;
}

// =============== GEMM1: relu(BN(z0 @ W1 + b1)), double-buffered ===============
// Grid (782, 4), 128 threads, 64 output cols per block (R11 layout).
__global__ void __launch_bounds__(128)
gemm1_kernel(int aSel, const float* __restrict__ B,
             const float* __restrict__ bias, const float* __restrict__ gma,
             const float* __restrict__ bta, int oSelLo, int oSelHi) {
    __shared__ unsigned AhS[2][128 * RSW], AlS[2][128 * RSW];
    __shared__ unsigned BhS[2][64 * RSW],  BlS[2][64 * RSW];
    const float* A = bufById(aSel);
    const int tid = threadIdx.x;
    const int lane = tid & 31, warp = tid >> 5;
    const int rowBase = blockIdx.x * 128;
    const int colBase = blockIdx.y * 64;
    const int g = lane >> 2, tg = lane & 3;
    const int kp = tid >> 4, nq = tid & 15;

    float acc[2][8][4];
#pragma unroll
    for (int m = 0; m < 2; m++)
#pragma unroll
        for (int nf = 0; nf < 8; nf++)
#pragma unroll
            for (int q = 0; q < 4; q++) acc[m][nf][q] = 0.f;

    float fA[16], fB[8];
    auto loadT = [&](int t) {
        int row = rowBase + tid;
        if (row < NN) {
            const float4* Ar = (const float4*)&A[row * 128 + t * 16];
#pragma unroll
            for (int j = 0; j < 4; j++) {
                float4 v = __ldg(&Ar[j]);
                fA[4 * j] = v.x; fA[4 * j + 1] = v.y;
                fA[4 * j + 2] = v.z; fA[4 * j + 3] = v.w;
            }
        } else {
#pragma unroll
            for (int j = 0; j < 16; j++) fA[j] = 0.f;
        }
        const float* Bp = &B[(t * 16 + 2 * kp) * 256 + colBase + 4 * nq];
        float4 r0 = __ldg((const float4*)Bp);
        float4 r1 = __ldg((const float4*)(Bp + 256));
        fB[0] = r0.x; fB[1] = r0.y; fB[2] = r0.z; fB[3] = r0.w;
        fB[4] = r1.x; fB[5] = r1.y; fB[6] = r1.z; fB[7] = r1.w;
    };
    auto storeT = [&](int buf) {
#pragma unroll
        for (int p = 0; p < 8; p++) {
            unsigned hi, lo;
            split2(fA[2 * p], fA[2 * p + 1], hi, lo);
            AhS[buf][tid * RSW + p] = hi;
            AlS[buf][tid * RSW + p] = lo;
        }
#pragma unroll
        for (int i = 0; i < 4; i++) {
            unsigned hi, lo;
            split2(fB[i], fB[4 + i], hi, lo);   // {B[k][n], B[k+1][n]}
            BhS[buf][(4 * nq + i) * RSW + kp] = hi;
            BlS[buf][(4 * nq + i) * RSW + kp] = lo;
        }
    };

    loadT(0);
    storeT(0);
    __syncthreads();

#pragma unroll 1
    for (int t = 0; t < 8; t++) {
        int buf = t & 1;
        if (t + 1 < 8) loadT(t + 1);

        unsigned ah[2][4], al[2][4];
#pragma unroll
        for (int m = 0; m < 2; m++) {
            int rb = warp * 32 + m * 16;
            int w0 = (rb + g) * RSW, w1 = (rb + g + 8) * RSW;
            ah[m][0] = AhS[buf][w0 + tg];     ah[m][1] = AhS[buf][w1 + tg];
            ah[m][2] = AhS[buf][w0 + 4 + tg]; ah[m][3] = AhS[buf][w1 + 4 + tg];
            al[m][0] = AlS[buf][w0 + tg];     al[m][1] = AlS[buf][w1 + tg];
            al[m][2] = AlS[buf][w0 + 4 + tg]; al[m][3] = AlS[buf][w1 + 4 + tg];
        }
#pragma unroll
        for (int nf = 0; nf < 8; nf++) {
            int wb = (nf * 8 + g) * RSW + tg;
            unsigned bh0 = BhS[buf][wb], bh1 = BhS[buf][wb + 4];
            unsigned bl0 = BlS[buf][wb], bl1 = BlS[buf][wb + 4];
#pragma unroll
            for (int m = 0; m < 2; m++) {
                mma_bf16(acc[m][nf], ah[m], bh0, bh1);
                mma_bf16(acc[m][nf], ah[m], bl0, bl1);
                mma_bf16(acc[m][nf], al[m], bh0, bh1);
            }
        }
        if (t + 1 < 8) storeT(buf ^ 1);
        __syncthreads();
    }

    float* Co = bufById(blockIdx.y < 2 ? oSelLo : oSelHi);
    int colLoc = colBase & 127;
#pragma unroll
    for (int nf = 0; nf < 8; nf++) {
        int colG = colBase + nf * 8 + tg * 2;
        int colL = colLoc + nf * 8 + tg * 2;
        float b0 = bias[colG], b1 = bias[colG + 1];
        float g0 = gma[colG],  g1 = gma[colG + 1];
        float e0 = bta[colG],  e1 = bta[colG + 1];
#pragma unroll
        for (int m = 0; m < 2; m++) {
            int r0 = rowBase + warp * 32 + m * 16 + g;
            if (r0 < NN) {
                float2 v;
                v.x = fmaxf((acc[m][nf][0] + b0) * g0 + e0, 0.f);
                v.y = fmaxf((acc[m][nf][1] + b1) * g1 + e1, 0.f);
                *(float2*)&Co[r0 * 128 + colL] = v;
            }
            int r1 = r0 + 8;
            if (r1 < NN) {
                float2 v;
                v.x = fmaxf((acc[m][nf][2] + b0) * g0 + e0, 0.f);
                v.y = fmaxf((acc[m][nf][3] + b1) * g1 + e1, 0.f);
                *(float2*)&Co[r1 * 128 + colL] = v;
            }
        }
    }
}

// =============== GEMM2: relu(z1 @ W2 + b2), double-buffered ====================
// Grid (782, 2), 128 threads, 64 output cols per block (R11 layout).
__global__ void __launch_bounds__(128)
gemm2_kernel(int aSelLo, int aSelHi, const float* __restrict__ B,
             const float* __restrict__ bias, int oSel) {
    __shared__ unsigned AhS[2][128 * RSW], AlS[2][128 * RSW];
    __shared__ unsigned BhS[2][64 * RSW],  BlS[2][64 * RSW];
    const float* A0 = bufById(aSelLo);
    const float* A1 = bufById(aSelHi);
    float* Co = bufById(oSel);
    const int tid = threadIdx.x;
    const int lane = tid & 31, warp = tid >> 5;
    const int rowBase = blockIdx.x * 128;
    const int colBase = blockIdx.y * 64;
    const int g = lane >> 2, tg = lane & 3;
    const int kp = tid >> 4, nq = tid & 15;

    float acc[2][8][4];
#pragma unroll
    for (int m = 0; m < 2; m++)
#pragma unroll
        for (int nf = 0; nf < 8; nf++)
#pragma unroll
            for (int q = 0; q < 4; q++) acc[m][nf][q] = 0.f;

    float fA[16], fB[8];
    auto loadT = [&](int t) {
        const float* Ab = (t < 8) ? A0 : A1;
        int kloc = (t & 7) * 16;
        int row = rowBase + tid;
        if (row < NN) {
            const float4* Ar = (const float4*)&Ab[row * 128 + kloc];
#pragma unroll
            for (int j = 0; j < 4; j++) {
                float4 v = __ldg(&Ar[j]);
                fA[4 * j] = v.x; fA[4 * j + 1] = v.y;
                fA[4 * j + 2] = v.z; fA[4 * j + 3] = v.w;
            }
        } else {
#pragma unroll
            for (int j = 0; j < 16; j++) fA[j] = 0.f;
        }
        const float* Bp = &B[(t * 16 + 2 * kp) * 128 + colBase + 4 * nq];
        float4 r0 = __ldg((const float4*)Bp);
        float4 r1 = __ldg((const float4*)(Bp + 128));
        fB[0] = r0.x; fB[1] = r0.y; fB[2] = r0.z; fB[3] = r0.w;
        fB[4] = r1.x; fB[5] = r1.y; fB[6] = r1.z; fB[7] = r1.w;
    };
    auto storeT = [&](int buf) {
#pragma unroll
        for (int p = 0; p < 8; p++) {
            unsigned hi, lo;
            split2(fA[2 * p], fA[2 * p + 1], hi, lo);
            AhS[buf][tid * RSW + p] = hi;
            AlS[buf][tid * RSW + p] = lo;
        }
#pragma unroll
        for (int i = 0; i < 4; i++) {
            unsigned hi, lo;
            split2(fB[i], fB[4 + i], hi, lo);
            BhS[buf][(4 * nq + i) * RSW + kp] = hi;
            BlS[buf][(4 * nq + i) * RSW + kp] = lo;
        }
    };

    loadT(0);
    storeT(0);
    __syncthreads();

#pragma unroll 1
    for (int t = 0; t < 16; t++) {
        int buf = t & 1;
        if (t + 1 < 16) loadT(t + 1);

        unsigned ah[2][4], al[2][4];
#pragma unroll
        for (int m = 0; m < 2; m++) {
            int rb = warp * 32 + m * 16;
            int w0 = (rb + g) * RSW, w1 = (rb + g + 8) * RSW;
            ah[m][0] = AhS[buf][w0 + tg];     ah[m][1] = AhS[buf][w1 + tg];
            ah[m][2] = AhS[buf][w0 + 4 + tg]; ah[m][3] = AhS[buf][w1 + 4 + tg];
            al[m][0] = AlS[buf][w0 + tg];     al[m][1] = AlS[buf][w1 + tg];
            al[m][2] = AlS[buf][w0 + 4 + tg]; al[m][3] = AlS[buf][w1 + 4 + tg];
        }
#pragma unroll
        for (int nf = 0; nf < 8; nf++) {
            int wb = (nf * 8 + g) * RSW + tg;
            unsigned bh0 = BhS[buf][wb], bh1 = BhS[buf][wb + 4];
            unsigned bl0 = BlS[buf][wb], bl1 = BlS[buf][wb + 4];
#pragma unroll
            for (int m = 0; m < 2; m++) {
                mma_bf16(acc[m][nf], ah[m], bh0, bh1);
                mma_bf16(acc[m][nf], ah[m], bl0, bl1);
                mma_bf16(acc[m][nf], al[m], bh0, bh1);
            }
        }
        if (t + 1 < 16) storeT(buf ^ 1);
        __syncthreads();
    }

#pragma unroll
    for (int nf = 0; nf < 8; nf++) {
        int col = colBase + nf * 8 + tg * 2;
        float b0 = bias[col], b1 = bias[col + 1];
#pragma unroll
        for (int m = 0; m < 2; m++) {
            int r0 = rowBase + warp * 32 + m * 16 + g;
            if (r0 < NN) {
                float2 v;
                v.x = fmaxf(acc[m][nf][0] + b0, 0.f);
                v.y = fmaxf(acc[m][nf][1] + b1, 0.f);
                *(float2*)&Co[r0 * 128 + col] = v;
            }
            int r1 = r0 + 8;
            if (r1 < NN) {
                float2 v;
                v.x = fmaxf(acc[m][nf][2] + b0, 0.f);
                v.y = fmaxf(acc[m][nf][3] + b1, 0.f);
                *(float2*)&Co[r1 * 128 + col] = v;
            }
        }
    }
}

// ---------------- pooling ----------------
__global__ void pool_kernel(const int* __restrict__ batch0) {
    int c = threadIdx.x;
    int start = blockIdx.x * 128;
    if (start >= NN) return;
    int end = start + 128; if (end > NN) end = NN;
    int cur = __ldg(&batch0[start]);
    float acc = 0.f;
    for (int i = start; i < end; i++) {
        int b = __ldg(&batch0[i]);
        float v = d_bufP[i * CC + c];
        if (b != cur) {
            atomicAdd(&d_g[cur * CC + c], acc);
            acc = 0.f;
            cur = b;
        }
        acc += v;
    }
    atomicAdd(&d_g[cur * CC + c], acc);
}

// ---------------- MLP head + log_softmax ----------------
__global__ void mlp_kernel(const float* __restrict__ pW1, const float* __restrict__ pb1,
                           const float* __restrict__ pW2, const float* __restrict__ pb2,
                           float* __restrict__ out) {
    __shared__ float sg[128];
    __shared__ float r0s[64], r1s[64];
    int gi = blockIdx.x, t = threadIdx.x;
    sg[t]      = d_g[gi * CC + t];
    sg[t + 64] = d_g[gi * CC + t + 64];
    __syncthreads();
    float acc = pb1[t];
#pragma unroll 8
    for (int k = 0; k < 128; k++) acc += sg[k] * pW1[k * 64 + t];
    float q = acc > 0.f ? acc : (expf(acc) - 1.f);
    r0s[t] = q * pW2[t * 2 + 0];
    r1s[t] = q * pW2[t * 2 + 1];
    __syncthreads();
    for (int off = 32; off > 0; off >>= 1) {
        if (t < off) { r0s[t] += r0s[t + off]; r1s[t] += r1s[t + off]; }
        __syncthreads();
    }
    if (t == 0) {
        float y0 = r0s[0] + pb2[0];
        float y1 = r1s[0] + pb2[1];
        float m = fmaxf(y0, y1);
        float lse = m + logf(expf(y0 - m) + expf(y1 - m));
        out[gi * 2 + 0] = y0 - lse;
        out[gi * 2 + 1] = y1 - lse;
    }
}

// ---------------- launch ----------------
extern "C" void kernel_launch(void* const* d_in, const int* in_sizes, int n_in,
                              void* d_out, int out_size) {
    const float* x    = (const float*)d_in[0];
    const int*   ei   = (const int*)  d_in[1];
    const int*   bat  = (const int*)  d_in[2];
    const float* ntW  = (const float*)d_in[3];
    const float* ntb  = (const float*)d_in[4];
    const float* W1   = (const float*)d_in[5];
    const float* b1   = (const float*)d_in[6];
    const float* g1   = (const float*)d_in[7];
    const float* be1  = (const float*)d_in[8];
    const float* W2   = (const float*)d_in[9];
    const float* b2   = (const float*)d_in[10];
    const float* pW1  = (const float*)d_in[11];
    const float* pb1  = (const float*)d_in[12];
    const float* pW2  = (const float*)d_in[13];
    const float* pb2  = (const float*)d_in[14];
    float* out = (float*)d_out;

    const int* src = ei;
    const int* dst = ei + EE;

    zero_deg_kernel<<<(NN + 255) / 256, 256>>>();
    node_transform_kernel<<<(NN * CC + 255) / 256, 256>>>(x, ntW, ntb);
    degree_kernel<<<(EE + 255) / 256, 256>>>(dst);
    scan1_kernel<<<SCAN_B, 1024>>>();
    scan2_kernel<<<1, 128>>>();
    scan3_kernel<<<SCAN_B, 1024>>>();
    fill_kernel<<<(EE + 255) / 256, 256>>>(src, dst);

    dim3 grid1((NN + 127) / 128, 4);
    dim3 grid2((NN + 127) / 128, 2);
    // Rotation (R11): even layer: h=P -> agg Q -> hidden (P,R) -> h=Q
    //                 odd  layer: h=Q -> agg P -> hidden (Q,R) -> h=P
    for (int l = 0; l < LL; l++) {
        int hin  = (l & 1) ? 1 : 0;
        int zbuf = (l & 1) ? 0 : 1;
        aggregate_kernel<<<(NN + 7) / 8, 256>>>(hin, zbuf);
        gemm1_kernel<<<grid1, 128>>>(zbuf, W1 + l * CC * 2 * CC,
                                     b1 + l * 2 * CC, g1 + l * 2 * CC,
                                     be1 + l * 2 * CC, hin, 2);
        gemm2_kernel<<<grid2, 128>>>(hin, 2, W2 + l * 2 * CC * CC,
                                     b2 + l * CC, zbuf);
    }
    // Final h in P after layer 3.

    zero_g_kernel<<<(GG * CC + 255) / 256, 256>>>();
    pool_kernel<<<(NN + 127) / 128, 128>>>(bat);
    mlp_kernel<<<GG, 64>>>(pW1, pb1, pW2, pb2, out);
}